// round 10
// baseline (speedup 1.0000x reference)
#include <cuda_runtime.h>
#include <cuda_bf16.h>
#include <cstdint>

// Problem constants
#define B     32
#define IN_CH 512
#define VD    16
#define HW    4096          // 64*64
#define NCLS  5

typedef unsigned long long ULL;

// ---------------- device scratch (no allocs allowed) ----------------
__device__ float g_v[(size_t)B * HW * VD];   // 8 MB: root conv output, (b, pix, 16)
__device__ float g_part[128 * VD];           // per-block partial sums of v (for mean)
__device__ float g_Asel[B * VD * VD];        // selected leaf composition matrix
__device__ float g_dvec[B * VD];             // selected leaf offset (A@root_b + c)
__device__ float g_m2part[256];              // per-block partial sums of m2

__device__ __forceinline__ ULL ffma2(ULL a, ULL b, ULL c) {
    ULL d;
    asm("fma.rn.f32x2 %0, %1, %2, %3;" : "=l"(d) : "l"(a), "l"(b), "l"(c));
    return d;
}
__device__ __forceinline__ ULL pack2(float lo, float hi) {
    float2 t = make_float2(lo, hi);
    return *reinterpret_cast<ULL*>(&t);
}
__device__ __forceinline__ float2 unpack2(ULL v) {
    return *reinterpret_cast<float2*>(&v);
}

// load one 8-channel group of this thread's 4 pixels (8 independent LDG.128)
__device__ __forceinline__ void load_group(ulonglong2* x, const float* fp, int cbase) {
#pragma unroll
    for (int u = 0; u < 8; u++)
        x[u] = *reinterpret_cast<const ulonglong2*>(fp + (size_t)(cbase + u) * HW);
}

// consume one 8-channel group: 32 ffma2 per channel pair-set
__device__ __forceinline__ void compute_group(const ulonglong2* x, const ULL* s_w,
                                              int cbase, ULL* acc0, ULL* acc1) {
#pragma unroll
    for (int u = 0; u < 8; u++) {
        const ulonglong2* wv = reinterpret_cast<const ulonglong2*>(s_w + (cbase + u) * VD);
#pragma unroll
        for (int q = 0; q < 8; q++) {
            ulonglong2 wp = wv[q];
            acc0[2 * q + 0] = ffma2(wp.x, x[u].x, acc0[2 * q + 0]);
            acc0[2 * q + 1] = ffma2(wp.y, x[u].x, acc0[2 * q + 1]);
            acc1[2 * q + 0] = ffma2(wp.x, x[u].y, acc1[2 * q + 0]);
            acc1[2 * q + 1] = ffma2(wp.y, x[u].y, acc1[2 * q + 1]);
        }
    }
}

// ======================================================================
// Pass 1: v[b,pix,:] = root_w @ features[b,:,pix]  (+ per-block partial sums)
// 256 threads/block, 4 consecutive pixels per thread, 4 blocks/batch (grid 128).
// Software-pipelined: group i+1's 8 LDG.128 issued BEFORE group i's FMAs,
// so each warp's compute phase hides the next group's DRAM latency.
// ======================================================================
__global__ void __launch_bounds__(256) k_root(const float* __restrict__ feat,
                                              const float* __restrict__ root_w) {
    extern __shared__ ULL s_w[];   // [512][16] duplicated (w,w) pairs = 64 KB
    const int b     = blockIdx.x >> 2;
    const int chunk = blockIdx.x & 3;
    const int tid   = threadIdx.x;

    for (int idx = tid; idx < IN_CH * VD; idx += 256) {
        int c = idx >> 4, o = idx & 15;
        float w = root_w[o * IN_CH + c];
        s_w[idx] = pack2(w, w);
    }
    __syncthreads();

    const int pix0 = chunk * 1024 + tid * 4;
    const float* fp = feat + (size_t)b * (IN_CH * HW) + pix0;

    ULL acc0[VD], acc1[VD];
    {
        ULL zu = pack2(0.f, 0.f);
#pragma unroll
        for (int o = 0; o < VD; o++) { acc0[o] = zu; acc1[o] = zu; }
    }

    ulonglong2 x0[8], x1[8];
    load_group(x0, fp, 0);

#pragma unroll 1
    for (int c0 = 0; c0 < IN_CH; c0 += 16) {
        load_group(x1, fp, c0 + 8);                   // prefetch group i+1
        compute_group(x0, s_w, c0, acc0, acc1);       // consume group i
        const int cn = (c0 + 16 < IN_CH) ? (c0 + 16) : 0;  // clamped dummy on last iter
        load_group(x0, fp, cn);                       // prefetch group i+2
        compute_group(x1, s_w, c0 + 8, acc0, acc1);   // consume group i+1
    }

    // unpack: acc0[o] = (pix0, pix0+1), acc1[o] = (pix0+2, pix0+3)
    float p0[VD], p1[VD], p2[VD], p3[VD];
#pragma unroll
    for (int o = 0; o < VD; o++) {
        float2 t0 = unpack2(acc0[o]);
        float2 t1 = unpack2(acc1[o]);
        p0[o] = t0.x; p1[o] = t0.y; p2[o] = t1.x; p3[o] = t1.y;
    }

    // store v (pixel-major, 16 contiguous floats per pixel) -> 256B/thread
    float4* vp = reinterpret_cast<float4*>(g_v + ((size_t)b * HW + pix0) * VD);
#pragma unroll
    for (int q = 0; q < 4; q++) {
        vp[0 * 4 + q] = make_float4(p0[4*q], p0[4*q+1], p0[4*q+2], p0[4*q+3]);
        vp[1 * 4 + q] = make_float4(p1[4*q], p1[4*q+1], p1[4*q+2], p1[4*q+3]);
        vp[2 * 4 + q] = make_float4(p2[4*q], p2[4*q+1], p2[4*q+2], p2[4*q+3]);
        vp[3 * 4 + q] = make_float4(p3[4*q], p3[4*q+1], p3[4*q+2], p3[4*q+3]);
    }

    // block reduction of per-pixel sums (deterministic; no atomics)
    __shared__ float red[8][VD];
    const int lane = tid & 31, wid = tid >> 5;
#pragma unroll
    for (int o = 0; o < VD; o++) {
        float s = (p0[o] + p1[o]) + (p2[o] + p3[o]);
#pragma unroll
        for (int off = 16; off; off >>= 1) s += __shfl_xor_sync(0xffffffffu, s, off);
        if (lane == 0) red[wid][o] = s;
    }
    __syncthreads();
    if (tid < VD) {
        float t = 0.f;
#pragma unroll
        for (int w = 0; w < 8; w++) t += red[w][tid];
        g_part[blockIdx.x * VD + tid] = t;
    }
}

// ======================================================================
// Pass 2: per-batch tree recursion on pooled means. One block per batch.
// ======================================================================
__global__ void __launch_bounds__(256) k_tree(const float* __restrict__ root_b,
                                              const float* __restrict__ level_w,
                                              const float* __restrict__ level_b,
                                              float* __restrict__ out) {
    const int b = blockIdx.x;
    const int tid = threadIdx.x;

    __shared__ float A[NCLS][VD][VD], Cv[NCLS][VD], Mu[NCLS][VD];
    __shared__ float An[NCLS][VD][VD], Cn[NCLS][VD], Mun[NCLS][VD];
    __shared__ float norms[NCLS];
    __shared__ int selsh;

    {
        int o = tid >> 4, i = tid & 15;
        A[0][o][i] = (o == i) ? 1.f : 0.f;
    }
    if (tid < VD) {
        float s = 0.f;
        for (int ch = 0; ch < 4; ch++) s += g_part[(b * 4 + ch) * VD + tid];
        Mu[0][tid] = s * (1.0f / (float)HW) + root_b[tid];
        Cv[0][tid] = 0.f;
    }
    __syncthreads();

    for (int level = 1; level < NCLS; level++) {
        const int prevN = level, newN = level + 1;
        const int off = ((level - 1) * (level + 2)) >> 1;   // 0,2,5,9

        if (tid < prevN) {
            float s = 0.f;
            for (int k = 0; k < VD; k++) s += Mu[tid][k] * Mu[tid][k];
            norms[tid] = sqrtf(s);
        }
        __syncthreads();

        if (tid < newN * VD) {
            const int node = tid >> 4, o = tid & 15;
            int pl = node - 1; if (pl < 0) pl = 0;
            int pr = node;     if (pr > prevN - 1) pr = prevN - 1;
            const int ps = (pl == pr) ? pl : ((norms[pr] > norms[pl]) ? pr : pl);

            const float* W = level_w + (off + node) * (VD * VD) + o * VD;
            const float bb = level_b[(off + node) * VD + o];
            float cm = bb, mm = bb;
            float arow[VD];
#pragma unroll
            for (int i = 0; i < VD; i++) arow[i] = 0.f;
            for (int k = 0; k < VD; k++) {
                const float w = W[k];
                cm += w * Cv[ps][k];
                mm += w * Mu[ps][k];
#pragma unroll
                for (int i = 0; i < VD; i++) arow[i] += w * A[ps][k][i];
            }
            Cn[node][o] = cm;
            Mun[node][o] = mm;
#pragma unroll
            for (int i = 0; i < VD; i++) An[node][o][i] = arow[i];
        }
        __syncthreads();

        for (int idx = tid; idx < newN * VD * VD; idx += 256) {
            int node = idx >> 8, r = idx & 255;
            A[node][r >> 4][r & 15] = An[node][r >> 4][r & 15];
        }
        if (tid < newN * VD) {
            Cv[tid >> 4][tid & 15] = Cn[tid >> 4][tid & 15];
            Mu[tid >> 4][tid & 15] = Mun[tid >> 4][tid & 15];
        }
        __syncthreads();
    }

    if (tid < NCLS) {
        float s = 0.f;
        for (int k = 0; k < VD; k++) s += Mu[tid][k] * Mu[tid][k];
        norms[tid] = sqrtf(s);
        out[b * NCLS + tid] = norms[tid];
    }
    __syncthreads();
    if (tid == 0) {
        int sel = 0; float best = norms[0];
        for (int n = 1; n < NCLS; n++) if (norms[n] > best) { best = norms[n]; sel = n; }
        selsh = sel;
        out[B * NCLS + B + b] = (float)sel;
    }
    __syncthreads();
    const int sel = selsh;
    g_Asel[b * 256 + tid] = A[sel][tid >> 4][tid & 15];
    if (tid < VD) {
        float s = Cv[sel][tid];
        for (int k = 0; k < VD; k++) s += A[sel][tid][k] * root_b[k];
        g_dvec[b * VD + tid] = s;
    }
}

// ======================================================================
// Pass 3: per-pixel f = A_sel@v + d, L2-normalize, MLP(64)+ReLU, scalar head.
// f32x2-packed over the thread's two pixels. 8 blocks/batch, 2 pixels/thread.
// ======================================================================
__global__ void __launch_bounds__(256) k_head(const float* __restrict__ m1_w,
                                              const float* __restrict__ m1_b,
                                              const float* __restrict__ m2_w,
                                              const float* __restrict__ m2_b) {
    __shared__ ULL sAp[VD * VD];      // A_sel duplicated pairs (2 KB)
    __shared__ ULL sdp[VD];           // d duplicated pairs
    __shared__ ULL sw1p[64 * VD];     // m1_w duplicated pairs (8 KB)
    __shared__ ULL sb1p[64];          // m1_b duplicated pairs
    __shared__ float sw2[64];
    __shared__ float sb2;
    const int b = blockIdx.x >> 3, chunk = blockIdx.x & 7;
    const int tid = threadIdx.x;

    {
        float a = g_Asel[b * 256 + tid];
        sAp[tid] = pack2(a, a);
    }
    for (int i = tid; i < 64 * VD; i += 256) {
        float w = m1_w[i];
        sw1p[i] = pack2(w, w);
    }
    if (tid < 64) {
        float bb = m1_b[tid];
        sb1p[tid] = pack2(bb, bb);
        sw2[tid] = m2_w[tid];
    }
    if (tid < VD) {
        float dv = g_dvec[b * VD + tid];
        sdp[tid] = pack2(dv, dv);
    }
    if (tid == 0) sb2 = m2_b[0];
    __syncthreads();

    const int pix0 = chunk * 512 + tid * 2;
    const float4* vp = reinterpret_cast<const float4*>(g_v + ((size_t)b * HW + pix0) * VD);

    float va0[VD], va1[VD];
#pragma unroll
    for (int q = 0; q < 4; q++) {
        float4 t0 = vp[q], t1 = vp[4 + q];
        va0[4*q+0] = t0.x; va0[4*q+1] = t0.y; va0[4*q+2] = t0.z; va0[4*q+3] = t0.w;
        va1[4*q+0] = t1.x; va1[4*q+1] = t1.y; va1[4*q+2] = t1.z; va1[4*q+3] = t1.w;
    }
    ULL v2[VD];
#pragma unroll
    for (int k = 0; k < VD; k++) v2[k] = pack2(va0[k], va1[k]);

    // f = A@v + d  (packed)
    ULL f2[VD];
#pragma unroll
    for (int o = 0; o < VD; o++) {
        ULL t = sdp[o];
#pragma unroll
        for (int k = 0; k < VD; k++) t = ffma2(sAp[o * VD + k], v2[k], t);
        f2[o] = t;
    }

    float n20 = 0.f, n21 = 0.f;
#pragma unroll
    for (int o = 0; o < VD; o++) {
        float2 t = unpack2(f2[o]);
        n20 += t.x * t.x; n21 += t.y * t.y;
    }
    const ULL inv2 = pack2(1.0f / (sqrtf(n20) + 1e-8f),
                           1.0f / (sqrtf(n21) + 1e-8f));

    float m2a0 = 0.f, m2a1 = 0.f;
#pragma unroll 8
    for (int j = 0; j < 64; j++) {
        ULL t2 = pack2(0.f, 0.f);
#pragma unroll
        for (int o = 0; o < VD; o++) t2 = ffma2(sw1p[j * VD + o], f2[o], t2);
        t2 = ffma2(t2, inv2, sb1p[j]);
        float2 t = unpack2(t2);
        m2a0 += sw2[j] * fmaxf(t.x, 0.f);
        m2a1 += sw2[j] * fmaxf(t.y, 0.f);
    }
    float ssum = (m2a0 + m2a1) + 2.0f * sb2;

    __shared__ float red[8];
    const int lane = tid & 31, wid = tid >> 5;
#pragma unroll
    for (int off = 16; off; off >>= 1) ssum += __shfl_xor_sync(0xffffffffu, ssum, off);
    if (lane == 0) red[wid] = ssum;
    __syncthreads();
    if (tid == 0) {
        float t = 0.f;
#pragma unroll
        for (int w = 0; w < 8; w++) t += red[w];
        g_m2part[blockIdx.x] = t;
    }
}

// ======================================================================
// Finisher: mantissa = sigmoid(mean(m2)) * 0.75 + 0.75
// ======================================================================
__global__ void k_fin(float* __restrict__ out) {
    const int b = threadIdx.x;
    if (b < B) {
        float s = 0.f;
        for (int c = 0; c < 8; c++) s += g_m2part[b * 8 + c];
        const float x = s * (1.0f / (float)HW);
        out[B * NCLS + b] = 0.75f / (1.0f + expf(-x)) + 0.75f;
    }
}

// ======================================================================
extern "C" void kernel_launch(void* const* d_in, const int* in_sizes, int n_in,
                              void* d_out, int out_size) {
    const float* features = (const float*)d_in[0];
    const float* root_w   = (const float*)d_in[1];
    const float* root_b   = (const float*)d_in[2];
    const float* level_w  = (const float*)d_in[3];
    const float* level_b  = (const float*)d_in[4];
    const float* m1_w     = (const float*)d_in[5];
    const float* m1_b     = (const float*)d_in[6];
    const float* m2_w     = (const float*)d_in[7];
    const float* m2_b     = (const float*)d_in[8];
    float* out = (float*)d_out;

    cudaFuncSetAttribute(k_root, cudaFuncAttributeMaxDynamicSharedMemorySize, 65536);

    k_root<<<B * 4, 256, 65536>>>(features, root_w);
    k_tree<<<B, 256>>>(root_b, level_w, level_b, out);
    k_head<<<B * 8, 256>>>(m1_w, m1_b, m2_w, m2_b);
    k_fin<<<1, 32>>>(out);
}

// round 11
// speedup vs baseline: 1.0515x; 1.0515x over previous
#include <cuda_runtime.h>
#include <cuda_bf16.h>
#include <cstdint>

// Problem constants
#define B     32
#define IN_CH 512
#define VD    16
#define HW    4096          // 64*64
#define NCLS  5

typedef unsigned long long ULL;

// ---------------- device scratch (no allocs allowed) ----------------
__device__ float g_v[(size_t)B * HW * VD];   // 8 MB: root conv output, (b, pix, 16)
__device__ float g_part[256 * VD];           // per-block partial sums of v (for mean)
__device__ float g_m2part[256];              // per-block partial sums of m2

__device__ __forceinline__ ULL ffma2(ULL a, ULL b, ULL c) {
    ULL d;
    asm("fma.rn.f32x2 %0, %1, %2, %3;" : "=l"(d) : "l"(a), "l"(b), "l"(c));
    return d;
}
__device__ __forceinline__ ULL pack2(float lo, float hi) {
    float2 t = make_float2(lo, hi);
    return *reinterpret_cast<ULL*>(&t);
}
__device__ __forceinline__ float2 unpack2(ULL v) {
    return *reinterpret_cast<float2*>(&v);
}

// load one 8-channel group of this thread's 2 pixels (8 independent LDG.64)
__device__ __forceinline__ void load_group(ULL* x, const float* fp, int cbase) {
#pragma unroll
    for (int u = 0; u < 8; u++)
        x[u] = *reinterpret_cast<const ULL*>(fp + (size_t)(cbase + u) * HW);
}

// consume one 8-channel group: 16 ffma2 per channel
__device__ __forceinline__ void compute_group(const ULL* x, const ULL* s_w,
                                              int cbase, ULL* acc) {
#pragma unroll
    for (int u = 0; u < 8; u++) {
        const ulonglong2* wv = reinterpret_cast<const ulonglong2*>(s_w + (cbase + u) * VD);
#pragma unroll
        for (int q = 0; q < 8; q++) {
            ulonglong2 wp = wv[q];
            acc[2 * q + 0] = ffma2(wp.x, x[u], acc[2 * q + 0]);
            acc[2 * q + 1] = ffma2(wp.y, x[u], acc[2 * q + 1]);
        }
    }
}

// ======================================================================
// Pass 1: v[b,pix,:] = root_w @ features[b,:,pix]  (+ per-block partial sums)
// 256 threads/block, 2 consecutive pixels per thread (one f32x2 lane pair),
// 8 blocks per batch -> grid 256, 2 CTAs/SM (16 warps/SM, 4/SMSP) for
// latency hiding. MLP=8 front-batched loads + ping-pong pipeline.
// ======================================================================
__global__ void __launch_bounds__(256, 2) k_root(const float* __restrict__ feat,
                                                 const float* __restrict__ root_w) {
    extern __shared__ ULL s_w[];   // [512][16] duplicated (w,w) pairs = 64 KB
    const int b     = blockIdx.x >> 3;
    const int chunk = blockIdx.x & 7;
    const int tid   = threadIdx.x;

    for (int idx = tid; idx < IN_CH * VD; idx += 256) {
        int c = idx >> 4, o = idx & 15;
        float w = root_w[o * IN_CH + c];
        s_w[idx] = pack2(w, w);
    }
    __syncthreads();

    const int pix0 = chunk * 512 + tid * 2;
    const float* fp = feat + (size_t)b * (IN_CH * HW) + pix0;

    ULL acc[VD];
    {
        ULL zu = pack2(0.f, 0.f);
#pragma unroll
        for (int o = 0; o < VD; o++) acc[o] = zu;
    }

    ULL x0[8], x1[8];
    load_group(x0, fp, 0);

#pragma unroll 1
    for (int c0 = 0; c0 < IN_CH; c0 += 16) {
        load_group(x1, fp, c0 + 8);                 // prefetch group i+1
        compute_group(x0, s_w, c0, acc);            // consume group i
        const int cn = (c0 + 16 < IN_CH) ? (c0 + 16) : 0;
        load_group(x0, fp, cn);                     // prefetch group i+2
        compute_group(x1, s_w, c0 + 8, acc);        // consume group i+1
    }

    // unpack: acc[o] = (pix0, pix0+1)
    float p0[VD], p1[VD];
#pragma unroll
    for (int o = 0; o < VD; o++) {
        float2 t = unpack2(acc[o]);
        p0[o] = t.x; p1[o] = t.y;
    }

    // store v (pixel-major, 16 contiguous floats per pixel) -> 128B/thread
    float4* vp = reinterpret_cast<float4*>(g_v + ((size_t)b * HW + pix0) * VD);
#pragma unroll
    for (int q = 0; q < 4; q++) {
        vp[q]     = make_float4(p0[4*q], p0[4*q+1], p0[4*q+2], p0[4*q+3]);
        vp[4 + q] = make_float4(p1[4*q], p1[4*q+1], p1[4*q+2], p1[4*q+3]);
    }

    // block reduction of per-pixel sums (deterministic; no atomics)
    __shared__ float red[8][VD];
    const int lane = tid & 31, wid = tid >> 5;
#pragma unroll
    for (int o = 0; o < VD; o++) {
        float s = p0[o] + p1[o];
#pragma unroll
        for (int off = 16; off; off >>= 1) s += __shfl_xor_sync(0xffffffffu, s, off);
        if (lane == 0) red[wid][o] = s;
    }
    __syncthreads();
    if (tid < VD) {
        float t = 0.f;
#pragma unroll
        for (int w = 0; w < 8; w++) t += red[w][tid];
        g_part[blockIdx.x * VD + tid] = t;
    }
}

// ======================================================================
// Pass 2 (fused tree + head): every block recomputes the tiny tree from
// g_part (identical, deterministic), then runs the per-pixel head on its
// 512-pixel chunk. chunk==0 block also writes logits + selected_class.
// grid 256 = 8 blocks/batch.
// ======================================================================
__global__ void __launch_bounds__(256) k_headtree(const float* __restrict__ root_b,
                                                  const float* __restrict__ level_w,
                                                  const float* __restrict__ level_b,
                                                  const float* __restrict__ m1_w,
                                                  const float* __restrict__ m1_b,
                                                  const float* __restrict__ m2_w,
                                                  const float* __restrict__ m2_b,
                                                  float* __restrict__ out) {
    const int b = blockIdx.x >> 3, chunk = blockIdx.x & 7;
    const int tid = threadIdx.x;

    // ---- tree phase (smem) ----
    __shared__ float A[NCLS][VD][VD], Cv[NCLS][VD], Mu[NCLS][VD];
    __shared__ float An[NCLS][VD][VD], Cn[NCLS][VD], Mun[NCLS][VD];
    __shared__ float norms[NCLS];
    __shared__ int selsh;

    {
        int o = tid >> 4, i = tid & 15;
        A[0][o][i] = (o == i) ? 1.f : 0.f;
    }
    if (tid < VD) {
        float s = 0.f;
        for (int ch = 0; ch < 8; ch++) s += g_part[(b * 8 + ch) * VD + tid];
        Mu[0][tid] = s * (1.0f / (float)HW) + root_b[tid];
        Cv[0][tid] = 0.f;
    }
    __syncthreads();

    for (int level = 1; level < NCLS; level++) {
        const int prevN = level, newN = level + 1;
        const int off = ((level - 1) * (level + 2)) >> 1;   // 0,2,5,9

        if (tid < prevN) {
            float s = 0.f;
            for (int k = 0; k < VD; k++) s += Mu[tid][k] * Mu[tid][k];
            norms[tid] = sqrtf(s);
        }
        __syncthreads();

        if (tid < newN * VD) {
            const int node = tid >> 4, o = tid & 15;
            int pl = node - 1; if (pl < 0) pl = 0;
            int pr = node;     if (pr > prevN - 1) pr = prevN - 1;
            const int ps = (pl == pr) ? pl : ((norms[pr] > norms[pl]) ? pr : pl);

            const float* W = level_w + (off + node) * (VD * VD) + o * VD;
            const float bb = level_b[(off + node) * VD + o];
            float cm = bb, mm = bb;
            float arow[VD];
#pragma unroll
            for (int i = 0; i < VD; i++) arow[i] = 0.f;
            for (int k = 0; k < VD; k++) {
                const float w = W[k];
                cm += w * Cv[ps][k];
                mm += w * Mu[ps][k];
#pragma unroll
                for (int i = 0; i < VD; i++) arow[i] += w * A[ps][k][i];
            }
            Cn[node][o] = cm;
            Mun[node][o] = mm;
#pragma unroll
            for (int i = 0; i < VD; i++) An[node][o][i] = arow[i];
        }
        __syncthreads();

        for (int idx = tid; idx < newN * VD * VD; idx += 256) {
            int node = idx >> 8, r = idx & 255;
            A[node][r >> 4][r & 15] = An[node][r >> 4][r & 15];
        }
        if (tid < newN * VD) {
            Cv[tid >> 4][tid & 15] = Cn[tid >> 4][tid & 15];
            Mu[tid >> 4][tid & 15] = Mun[tid >> 4][tid & 15];
        }
        __syncthreads();
    }

    if (tid < NCLS) {
        float s = 0.f;
        for (int k = 0; k < VD; k++) s += Mu[tid][k] * Mu[tid][k];
        norms[tid] = sqrtf(s);
        if (chunk == 0) out[b * NCLS + tid] = norms[tid];
    }
    __syncthreads();
    if (tid == 0) {
        int sel = 0; float best = norms[0];
        for (int n = 1; n < NCLS; n++) if (norms[n] > best) { best = norms[n]; sel = n; }
        selsh = sel;
        if (chunk == 0) out[B * NCLS + B + b] = (float)sel;
    }
    __syncthreads();
    const int sel = selsh;

    // ---- head setup: duplicated-pair weights in smem ----
    __shared__ ULL sAp[VD * VD];
    __shared__ ULL sdp[VD];
    __shared__ ULL sw1p[64 * VD];
    __shared__ ULL sb1p[64];
    __shared__ float sw2[64];
    __shared__ float sb2;

    {
        float a = A[sel][tid >> 4][tid & 15];
        sAp[tid] = pack2(a, a);
    }
    for (int i = tid; i < 64 * VD; i += 256) {
        float w = m1_w[i];
        sw1p[i] = pack2(w, w);
    }
    if (tid < 64) {
        float bb = m1_b[tid];
        sb1p[tid] = pack2(bb, bb);
        sw2[tid] = m2_w[tid];
    }
    if (tid < VD) {
        float s = Cv[sel][tid];
        for (int k = 0; k < VD; k++) s += A[sel][tid][k] * root_b[k];
        sdp[tid] = pack2(s, s);
    }
    if (tid == 0) sb2 = m2_b[0];
    __syncthreads();

    // ---- head phase: 2 pixels/thread, f32x2-packed ----
    const int pix0 = chunk * 512 + tid * 2;
    const float4* vp = reinterpret_cast<const float4*>(g_v + ((size_t)b * HW + pix0) * VD);

    float va0[VD], va1[VD];
#pragma unroll
    for (int q = 0; q < 4; q++) {
        float4 t0 = vp[q], t1 = vp[4 + q];
        va0[4*q+0] = t0.x; va0[4*q+1] = t0.y; va0[4*q+2] = t0.z; va0[4*q+3] = t0.w;
        va1[4*q+0] = t1.x; va1[4*q+1] = t1.y; va1[4*q+2] = t1.z; va1[4*q+3] = t1.w;
    }
    ULL v2[VD];
#pragma unroll
    for (int k = 0; k < VD; k++) v2[k] = pack2(va0[k], va1[k]);

    ULL f2[VD];
#pragma unroll
    for (int o = 0; o < VD; o++) {
        ULL t = sdp[o];
#pragma unroll
        for (int k = 0; k < VD; k++) t = ffma2(sAp[o * VD + k], v2[k], t);
        f2[o] = t;
    }

    float n20 = 0.f, n21 = 0.f;
#pragma unroll
    for (int o = 0; o < VD; o++) {
        float2 t = unpack2(f2[o]);
        n20 += t.x * t.x; n21 += t.y * t.y;
    }
    const ULL inv2 = pack2(1.0f / (sqrtf(n20) + 1e-8f),
                           1.0f / (sqrtf(n21) + 1e-8f));

    float m2a0 = 0.f, m2a1 = 0.f;
#pragma unroll 8
    for (int j = 0; j < 64; j++) {
        ULL t2 = pack2(0.f, 0.f);
#pragma unroll
        for (int o = 0; o < VD; o++) t2 = ffma2(sw1p[j * VD + o], f2[o], t2);
        t2 = ffma2(t2, inv2, sb1p[j]);
        float2 t = unpack2(t2);
        m2a0 += sw2[j] * fmaxf(t.x, 0.f);
        m2a1 += sw2[j] * fmaxf(t.y, 0.f);
    }
    float ssum = (m2a0 + m2a1) + 2.0f * sb2;

    __shared__ float red[8];
    const int lane = tid & 31, wid = tid >> 5;
#pragma unroll
    for (int off = 16; off; off >>= 1) ssum += __shfl_xor_sync(0xffffffffu, ssum, off);
    if (lane == 0) red[wid] = ssum;
    __syncthreads();
    if (tid == 0) {
        float t = 0.f;
#pragma unroll
        for (int w = 0; w < 8; w++) t += red[w];
        g_m2part[blockIdx.x] = t;
    }
}

// ======================================================================
// Finisher: mantissa = sigmoid(mean(m2)) * 0.75 + 0.75
// ======================================================================
__global__ void k_fin(float* __restrict__ out) {
    const int b = threadIdx.x;
    if (b < B) {
        float s = 0.f;
        for (int c = 0; c < 8; c++) s += g_m2part[b * 8 + c];
        const float x = s * (1.0f / (float)HW);
        out[B * NCLS + b] = 0.75f / (1.0f + expf(-x)) + 0.75f;
    }
}

// ======================================================================
extern "C" void kernel_launch(void* const* d_in, const int* in_sizes, int n_in,
                              void* d_out, int out_size) {
    const float* features = (const float*)d_in[0];
    const float* root_w   = (const float*)d_in[1];
    const float* root_b   = (const float*)d_in[2];
    const float* level_w  = (const float*)d_in[3];
    const float* level_b  = (const float*)d_in[4];
    const float* m1_w     = (const float*)d_in[5];
    const float* m1_b     = (const float*)d_in[6];
    const float* m2_w     = (const float*)d_in[7];
    const float* m2_b     = (const float*)d_in[8];
    float* out = (float*)d_out;

    cudaFuncSetAttribute(k_root, cudaFuncAttributeMaxDynamicSharedMemorySize, 65536);

    k_root<<<B * 8, 256, 65536>>>(features, root_w);
    k_headtree<<<B * 8, 256>>>(root_b, level_w, level_b, m1_w, m1_b, m2_w, m2_b, out);
    k_fin<<<1, 32>>>(out);
}

// round 12
// speedup vs baseline: 1.1897x; 1.1314x over previous
#include <cuda_runtime.h>
#include <cuda_bf16.h>
#include <cstdint>

// Problem constants
#define B     32
#define IN_CH 512
#define VD    16
#define HW    4096          // 64*64
#define NCLS  5

typedef unsigned long long ULL;

// ---------------- device scratch (no allocs allowed) ----------------
__device__ float g_v[(size_t)B * HW * VD];   // 8 MB: root conv output, (b, pix, 16)
__device__ float g_part[512 * VD];           // per-block partial sums of v (16 chunks/batch)
__device__ float g_m2part[256];              // per-block partial sums of m2

__device__ __forceinline__ ULL ffma2(ULL a, ULL b, ULL c) {
    ULL d;
    asm("fma.rn.f32x2 %0, %1, %2, %3;" : "=l"(d) : "l"(a), "l"(b), "l"(c));
    return d;
}
__device__ __forceinline__ ULL pack2(float lo, float hi) {
    float2 t = make_float2(lo, hi);
    return *reinterpret_cast<ULL*>(&t);
}
__device__ __forceinline__ float2 unpack2(ULL v) {
    return *reinterpret_cast<float2*>(&v);
}
__device__ __forceinline__ uint32_t f2tf32(float x) {
    uint32_t r;
    asm("cvt.rna.tf32.f32 %0, %1;" : "=r"(r) : "f"(x));
    return r;
}
__device__ __forceinline__ void mma_tf32(float* d, const uint32_t* a, uint32_t b0, uint32_t b1) {
    asm volatile(
        "mma.sync.aligned.m16n8k8.row.col.f32.tf32.tf32.f32 "
        "{%0,%1,%2,%3}, {%4,%5,%6,%7}, {%8,%9}, {%0,%1,%2,%3};"
        : "+f"(d[0]), "+f"(d[1]), "+f"(d[2]), "+f"(d[3])
        : "r"(a[0]), "r"(a[1]), "r"(a[2]), "r"(a[3]), "r"(b0), "r"(b1));
}

// ======================================================================
// Pass 1 (tensor-core): v[b,pix,:] = root_w @ features[b,:,pix]
// mma.sync m16n8k8 tf32. Warp = 32 pixels x 16 outs; CTA = 8 warps = 256 px.
// Grid = 512 (16 chunks/batch). Weights tf32 in smem, transposed, stride 24
// (bank-conflict-free for the B-fragment pattern). A read directly from GMEM
// (one full 32B sector per LDG.32, every element read exactly once).
// ======================================================================
#define WSTRIDE 24
__global__ void __launch_bounds__(256, 4) k_root(const float* __restrict__ feat,
                                                 const float* __restrict__ root_w) {
    __shared__ uint32_t s_wt[IN_CH * WSTRIDE];   // 48KB: tf32 weights [ch][out]
    __shared__ float sred[8][VD];

    const int b     = blockIdx.x >> 4;
    const int chunk = blockIdx.x & 15;
    const int tid   = threadIdx.x;
    const int warp  = tid >> 5, lane = tid & 31;
    const int gid   = lane >> 2, tg = lane & 3;

    // stage weights: s_wt[ch][out] = tf32(root_w[out][ch])
    for (int idx = tid; idx < VD * IN_CH; idx += 256) {
        int o = idx >> 9;          // out   (root_w is [16][512] row-major)
        int c = idx & 511;         // channel
        s_wt[c * WSTRIDE + o] = f2tf32(root_w[idx]);
    }
    __syncthreads();

    const int pix0 = chunk * 256 + warp * 32;
    // thread's A base: channel tg, pixel pix0+gid
    const float* fp = feat + (size_t)b * (IN_CH * HW) + (size_t)tg * HW + pix0 + gid;

    float d[2][2][4];   // [m-tile][n-half][4]
#pragma unroll
    for (int t = 0; t < 2; t++)
#pragma unroll
        for (int h = 0; h < 2; h++)
#pragma unroll
            for (int j = 0; j < 4; j++) d[t][h][j] = 0.f;

#pragma unroll 2
    for (int k0 = 0; k0 < IN_CH; k0 += 8) {
        // A fragments: rows gid/gid+8 (+t*16 pixels), cols tg/tg+4 (channels)
        float af[2][4];
#pragma unroll
        for (int t = 0; t < 2; t++) {
            af[t][0] = fp[t * 16];
            af[t][1] = fp[t * 16 + 8];
            af[t][2] = fp[(size_t)4 * HW + t * 16];
            af[t][3] = fp[(size_t)4 * HW + t * 16 + 8];
        }
        uint32_t a[2][4];
#pragma unroll
        for (int t = 0; t < 2; t++)
#pragma unroll
            for (int j = 0; j < 4; j++) a[t][j] = f2tf32(af[t][j]);

        // B fragments: b0 = W^T[k0+tg][n], b1 = W^T[k0+tg+4][n], n = h*8+gid
        const uint32_t* wr0 = s_wt + (k0 + tg) * WSTRIDE;
        const uint32_t* wr1 = wr0 + 4 * WSTRIDE;
        uint32_t b00 = wr0[gid],     b10 = wr1[gid];       // h=0
        uint32_t b01 = wr0[8 + gid], b11 = wr1[8 + gid];   // h=1

        mma_tf32(d[0][0], a[0], b00, b10);
        mma_tf32(d[0][1], a[0], b01, b11);
        mma_tf32(d[1][0], a[1], b00, b10);
        mma_tf32(d[1][1], a[1], b01, b11);

        fp += (size_t)8 * HW;
    }

    // ---- store v: D[pix][out], thread owns rows gid/gid+8 (+t*16), cols h*8+2tg..+1
    float* vb = g_v + ((size_t)b * HW + pix0) * VD;
#pragma unroll
    for (int t = 0; t < 2; t++) {
#pragma unroll
        for (int h = 0; h < 2; h++) {
            *reinterpret_cast<float2*>(vb + (t * 16 + gid) * VD + h * 8 + 2 * tg) =
                make_float2(d[t][h][0], d[t][h][1]);
            *reinterpret_cast<float2*>(vb + (t * 16 + gid + 8) * VD + h * 8 + 2 * tg) =
                make_float2(d[t][h][2], d[t][h][3]);
        }
    }

    // ---- pooled sums over this warp's 32 pixels, per out column
    float s[2][2];  // [h][col parity]: cols h*8 + 2tg + p
#pragma unroll
    for (int h = 0; h < 2; h++) {
        s[h][0] = d[0][h][0] + d[0][h][2] + d[1][h][0] + d[1][h][2];
        s[h][1] = d[0][h][1] + d[0][h][3] + d[1][h][1] + d[1][h][3];
    }
#pragma unroll
    for (int off = 4; off < 32; off <<= 1) {
#pragma unroll
        for (int h = 0; h < 2; h++) {
            s[h][0] += __shfl_xor_sync(0xffffffffu, s[h][0], off);
            s[h][1] += __shfl_xor_sync(0xffffffffu, s[h][1], off);
        }
    }
    if (gid == 0) {
#pragma unroll
        for (int h = 0; h < 2; h++) {
            sred[warp][h * 8 + 2 * tg]     = s[h][0];
            sred[warp][h * 8 + 2 * tg + 1] = s[h][1];
        }
    }
    __syncthreads();
    if (tid < VD) {
        float t = 0.f;
#pragma unroll
        for (int w = 0; w < 8; w++) t += sred[w][tid];
        g_part[blockIdx.x * VD + tid] = t;
    }
}

// ======================================================================
// Pass 2 (fused tree + head): every block recomputes the tiny tree from
// g_part (identical, deterministic), then runs the per-pixel head on its
// 512-pixel chunk. chunk==0 block also writes logits + selected_class.
// grid 256 = 8 blocks/batch.
// ======================================================================
__global__ void __launch_bounds__(256) k_headtree(const float* __restrict__ root_b,
                                                  const float* __restrict__ level_w,
                                                  const float* __restrict__ level_b,
                                                  const float* __restrict__ m1_w,
                                                  const float* __restrict__ m1_b,
                                                  const float* __restrict__ m2_w,
                                                  const float* __restrict__ m2_b,
                                                  float* __restrict__ out) {
    const int b = blockIdx.x >> 3, chunk = blockIdx.x & 7;
    const int tid = threadIdx.x;

    // ---- tree phase (smem) ----
    __shared__ float A[NCLS][VD][VD], Cv[NCLS][VD], Mu[NCLS][VD];
    __shared__ float An[NCLS][VD][VD], Cn[NCLS][VD], Mun[NCLS][VD];
    __shared__ float norms[NCLS];
    __shared__ int selsh;

    {
        int o = tid >> 4, i = tid & 15;
        A[0][o][i] = (o == i) ? 1.f : 0.f;
    }
    if (tid < VD) {
        float s = 0.f;
        for (int ch = 0; ch < 16; ch++) s += g_part[(b * 16 + ch) * VD + tid];
        Mu[0][tid] = s * (1.0f / (float)HW) + root_b[tid];
        Cv[0][tid] = 0.f;
    }
    __syncthreads();

    for (int level = 1; level < NCLS; level++) {
        const int prevN = level, newN = level + 1;
        const int off = ((level - 1) * (level + 2)) >> 1;   // 0,2,5,9

        if (tid < prevN) {
            float s = 0.f;
            for (int k = 0; k < VD; k++) s += Mu[tid][k] * Mu[tid][k];
            norms[tid] = sqrtf(s);
        }
        __syncthreads();

        if (tid < newN * VD) {
            const int node = tid >> 4, o = tid & 15;
            int pl = node - 1; if (pl < 0) pl = 0;
            int pr = node;     if (pr > prevN - 1) pr = prevN - 1;
            const int ps = (pl == pr) ? pl : ((norms[pr] > norms[pl]) ? pr : pl);

            const float* W = level_w + (off + node) * (VD * VD) + o * VD;
            const float bb = level_b[(off + node) * VD + o];
            float cm = bb, mm = bb;
            float arow[VD];
#pragma unroll
            for (int i = 0; i < VD; i++) arow[i] = 0.f;
            for (int k = 0; k < VD; k++) {
                const float w = W[k];
                cm += w * Cv[ps][k];
                mm += w * Mu[ps][k];
#pragma unroll
                for (int i = 0; i < VD; i++) arow[i] += w * A[ps][k][i];
            }
            Cn[node][o] = cm;
            Mun[node][o] = mm;
#pragma unroll
            for (int i = 0; i < VD; i++) An[node][o][i] = arow[i];
        }
        __syncthreads();

        for (int idx = tid; idx < newN * VD * VD; idx += 256) {
            int node = idx >> 8, r = idx & 255;
            A[node][r >> 4][r & 15] = An[node][r >> 4][r & 15];
        }
        if (tid < newN * VD) {
            Cv[tid >> 4][tid & 15] = Cn[tid >> 4][tid & 15];
            Mu[tid >> 4][tid & 15] = Mun[tid >> 4][tid & 15];
        }
        __syncthreads();
    }

    if (tid < NCLS) {
        float s = 0.f;
        for (int k = 0; k < VD; k++) s += Mu[tid][k] * Mu[tid][k];
        norms[tid] = sqrtf(s);
        if (chunk == 0) out[b * NCLS + tid] = norms[tid];
    }
    __syncthreads();
    if (tid == 0) {
        int sel = 0; float best = norms[0];
        for (int n = 1; n < NCLS; n++) if (norms[n] > best) { best = norms[n]; sel = n; }
        selsh = sel;
        if (chunk == 0) out[B * NCLS + B + b] = (float)sel;
    }
    __syncthreads();
    const int sel = selsh;

    // ---- head setup: duplicated-pair weights in smem ----
    __shared__ ULL sAp[VD * VD];
    __shared__ ULL sdp[VD];
    __shared__ ULL sw1p[64 * VD];
    __shared__ ULL sb1p[64];
    __shared__ float sw2[64];
    __shared__ float sb2;

    {
        float a = A[sel][tid >> 4][tid & 15];
        sAp[tid] = pack2(a, a);
    }
    for (int i = tid; i < 64 * VD; i += 256) {
        float w = m1_w[i];
        sw1p[i] = pack2(w, w);
    }
    if (tid < 64) {
        float bb = m1_b[tid];
        sb1p[tid] = pack2(bb, bb);
        sw2[tid] = m2_w[tid];
    }
    if (tid < VD) {
        float s = Cv[sel][tid];
        for (int k = 0; k < VD; k++) s += A[sel][tid][k] * root_b[k];
        sdp[tid] = pack2(s, s);
    }
    if (tid == 0) sb2 = m2_b[0];
    __syncthreads();

    // ---- head phase: 2 pixels/thread, f32x2-packed ----
    const int pix0 = chunk * 512 + tid * 2;
    const float4* vp = reinterpret_cast<const float4*>(g_v + ((size_t)b * HW + pix0) * VD);

    float va0[VD], va1[VD];
#pragma unroll
    for (int q = 0; q < 4; q++) {
        float4 t0 = vp[q], t1 = vp[4 + q];
        va0[4*q+0] = t0.x; va0[4*q+1] = t0.y; va0[4*q+2] = t0.z; va0[4*q+3] = t0.w;
        va1[4*q+0] = t1.x; va1[4*q+1] = t1.y; va1[4*q+2] = t1.z; va1[4*q+3] = t1.w;
    }
    ULL v2[VD];
#pragma unroll
    for (int k = 0; k < VD; k++) v2[k] = pack2(va0[k], va1[k]);

    ULL f2[VD];
#pragma unroll
    for (int o = 0; o < VD; o++) {
        ULL t = sdp[o];
#pragma unroll
        for (int k = 0; k < VD; k++) t = ffma2(sAp[o * VD + k], v2[k], t);
        f2[o] = t;
    }

    float n20 = 0.f, n21 = 0.f;
#pragma unroll
    for (int o = 0; o < VD; o++) {
        float2 t = unpack2(f2[o]);
        n20 += t.x * t.x; n21 += t.y * t.y;
    }
    const ULL inv2 = pack2(1.0f / (sqrtf(n20) + 1e-8f),
                           1.0f / (sqrtf(n21) + 1e-8f));

    float m2a0 = 0.f, m2a1 = 0.f;
#pragma unroll 8
    for (int j = 0; j < 64; j++) {
        ULL t2 = pack2(0.f, 0.f);
#pragma unroll
        for (int o = 0; o < VD; o++) t2 = ffma2(sw1p[j * VD + o], f2[o], t2);
        t2 = ffma2(t2, inv2, sb1p[j]);
        float2 t = unpack2(t2);
        m2a0 += sw2[j] * fmaxf(t.x, 0.f);
        m2a1 += sw2[j] * fmaxf(t.y, 0.f);
    }
    float ssum = (m2a0 + m2a1) + 2.0f * sb2;

    __shared__ float red[8];
    const int lane = tid & 31, wid = tid >> 5;
#pragma unroll
    for (int off = 16; off; off >>= 1) ssum += __shfl_xor_sync(0xffffffffu, ssum, off);
    if (lane == 0) red[wid] = ssum;
    __syncthreads();
    if (tid == 0) {
        float t = 0.f;
#pragma unroll
        for (int w = 0; w < 8; w++) t += red[w];
        g_m2part[blockIdx.x] = t;
    }
}

// ======================================================================
// Finisher: mantissa = sigmoid(mean(m2)) * 0.75 + 0.75
// ======================================================================
__global__ void k_fin(float* __restrict__ out) {
    const int b = threadIdx.x;
    if (b < B) {
        float s = 0.f;
        for (int c = 0; c < 8; c++) s += g_m2part[b * 8 + c];
        const float x = s * (1.0f / (float)HW);
        out[B * NCLS + b] = 0.75f / (1.0f + expf(-x)) + 0.75f;
    }
}

// ======================================================================
extern "C" void kernel_launch(void* const* d_in, const int* in_sizes, int n_in,
                              void* d_out, int out_size) {
    const float* features = (const float*)d_in[0];
    const float* root_w   = (const float*)d_in[1];
    const float* root_b   = (const float*)d_in[2];
    const float* level_w  = (const float*)d_in[3];
    const float* level_b  = (const float*)d_in[4];
    const float* m1_w     = (const float*)d_in[5];
    const float* m1_b     = (const float*)d_in[6];
    const float* m2_w     = (const float*)d_in[7];
    const float* m2_b     = (const float*)d_in[8];
    float* out = (float*)d_out;

    k_root<<<B * 16, 256>>>(features, root_w);
    k_headtree<<<B * 8, 256>>>(root_b, level_w, level_b, m1_w, m1_b, m2_w, m2_b, out);
    k_fin<<<1, 32>>>(out);
}

// round 13
// speedup vs baseline: 1.5605x; 1.3117x over previous
#include <cuda_runtime.h>
#include <cuda_bf16.h>
#include <cstdint>

// Problem constants
#define B     32
#define IN_CH 512
#define VD    16
#define HW    4096          // 64*64
#define NCLS  5
#define KSTEPS 64           // IN_CH / 8

typedef unsigned long long ULL;

// ---------------- device scratch (no allocs allowed) ----------------
__device__ float g_v[(size_t)B * HW * VD];   // 8 MB: root conv output, (b, slot, 16)
__device__ float g_part[512 * VD];           // per-block partial sums of v
__device__ float g_m2part[256];              // per-block partial sums of m2
__device__ int   g_ticket;                   // last-block ticket (reset each launch)

__device__ __forceinline__ ULL ffma2(ULL a, ULL b, ULL c) {
    ULL d;
    asm("fma.rn.f32x2 %0, %1, %2, %3;" : "=l"(d) : "l"(a), "l"(b), "l"(c));
    return d;
}
__device__ __forceinline__ ULL pack2(float lo, float hi) {
    float2 t = make_float2(lo, hi);
    return *reinterpret_cast<ULL*>(&t);
}
__device__ __forceinline__ float2 unpack2(ULL v) {
    return *reinterpret_cast<float2*>(&v);
}
__device__ __forceinline__ uint32_t f2tf32(float x) {
    uint32_t r;
    asm("cvt.rna.tf32.f32 %0, %1;" : "=r"(r) : "f"(x));
    return r;
}
__device__ __forceinline__ void mma_tf32(float* d, const uint32_t* a, uint32_t b0, uint32_t b1) {
    asm volatile(
        "mma.sync.aligned.m16n8k8.row.col.f32.tf32.tf32.f32 "
        "{%0,%1,%2,%3}, {%4,%5,%6,%7}, {%8,%9}, {%0,%1,%2,%3};"
        : "+f"(d[0]), "+f"(d[1]), "+f"(d[2]), "+f"(d[3])
        : "r"(a[0]), "r"(a[1]), "r"(a[2]), "r"(a[3]), "r"(b0), "r"(b1));
}

// ======================================================================
// Pass 1 (tensor-core, full-line loads): v = root_w @ features per pixel.
// Warp = 32 pixels x 16 outs. Per k-step (8 ch):
//   2x LDG.128 (4 consecutive px, 1 ch each) -> 8 full 128B lines/warp
//   8x shfl.idx redistribute to mma fragment layout (uniform reg index via
//     pixel permutation: m-row r <-> pixel 4*(r&7) + (r>>3))
//   2x LDS.64 of fragment-order tf32 weights, 4x mma.
// Pixel slots within each 32-px tile are stored PERMUTED — all consumers
// (per-pixel head, pooled mean) are permutation-invariant.
// ======================================================================
__global__ void __launch_bounds__(256, 4) k_root(const float* __restrict__ feat,
                                                 const float* __restrict__ root_w) {
    __shared__ uint2 s_bl[KSTEPS * 32];   // 16KB: b-frags for out cols 0-7
    __shared__ uint2 s_bh[KSTEPS * 32];   // 16KB: b-frags for out cols 8-15
    __shared__ float sred[8][VD];

    const int b     = blockIdx.x >> 4;
    const int chunk = blockIdx.x & 15;
    const int tid   = threadIdx.x;
    const int warp  = tid >> 5, lane = tid & 31;
    const int gid   = lane >> 2, tg = lane & 3;

    // stage B in fragment order: for (s, lane=(gid,tg)):
    //   s_bl[s][lane] = { W[gid][8s+tg],   W[gid][8s+tg+4]   }  (tf32)
    //   s_bh[s][lane] = { W[gid+8][8s+tg], W[gid+8][8s+tg+4] }
    for (int idx = tid; idx < KSTEPS * 32; idx += 256) {
        int s = idx >> 5, l = idx & 31;
        int g = l >> 2, t = l & 3;
        int k = 8 * s + t;
        s_bl[idx] = make_uint2(f2tf32(root_w[g * IN_CH + k]),
                               f2tf32(root_w[g * IN_CH + k + 4]));
        s_bh[idx] = make_uint2(f2tf32(root_w[(g + 8) * IN_CH + k]),
                               f2tf32(root_w[(g + 8) * IN_CH + k + 4]));
    }
    __syncthreads();

    const int pix0 = chunk * 256 + warp * 32;
    // this thread's A-load: channel lane>>3 (+8s / +4), pixels 4*(lane&7)..+3
    const float* lp = feat + (size_t)b * (IN_CH * HW) + (size_t)(lane >> 3) * HW
                    + pix0 + 4 * (lane & 7);
    const int src = (tg << 3) | gid;   // shfl source lane (fixed)

    float d[2][2][4];
#pragma unroll
    for (int t = 0; t < 2; t++)
#pragma unroll
        for (int h = 0; h < 2; h++)
#pragma unroll
            for (int j = 0; j < 4; j++) d[t][h][j] = 0.f;

    float4 c1 = *reinterpret_cast<const float4*>(lp);
    float4 c2 = *reinterpret_cast<const float4*>(lp + (size_t)4 * HW);

#pragma unroll 4
    for (int s = 0; s < KSTEPS; s++) {
        // prefetch next k-step (wraps to 0 on last iter: dummy, cheap)
        const float* np = lp + (size_t)(((s + 1) & (KSTEPS - 1)) * 8) * HW;
        float4 n1 = *reinterpret_cast<const float4*>(np);
        float4 n2 = *reinterpret_cast<const float4*>(np + (size_t)4 * HW);

        // convert own data, then redistribute to fragment layout
        uint32_t u1x = f2tf32(c1.x), u1y = f2tf32(c1.y), u1z = f2tf32(c1.z), u1w = f2tf32(c1.w);
        uint32_t u2x = f2tf32(c2.x), u2y = f2tf32(c2.y), u2z = f2tf32(c2.z), u2w = f2tf32(c2.w);

        uint32_t a0[4], a1[4];
        a0[0] = __shfl_sync(0xffffffffu, u1x, src);
        a0[1] = __shfl_sync(0xffffffffu, u1y, src);
        a1[0] = __shfl_sync(0xffffffffu, u1z, src);
        a1[1] = __shfl_sync(0xffffffffu, u1w, src);
        a0[2] = __shfl_sync(0xffffffffu, u2x, src);
        a0[3] = __shfl_sync(0xffffffffu, u2y, src);
        a1[2] = __shfl_sync(0xffffffffu, u2z, src);
        a1[3] = __shfl_sync(0xffffffffu, u2w, src);

        uint2 bl = s_bl[(s << 5) | lane];
        uint2 bh = s_bh[(s << 5) | lane];

        mma_tf32(d[0][0], a0, bl.x, bl.y);
        mma_tf32(d[0][1], a0, bh.x, bh.y);
        mma_tf32(d[1][0], a1, bl.x, bl.y);
        mma_tf32(d[1][1], a1, bh.x, bh.y);

        c1 = n1; c2 = n2;
    }

    // ---- store v (permuted pixel slots within the 32-px tile) ----
    // m-row (tile t, local row gid / gid+8) -> slot 4*gid + 2*t + jj
    float* vb = g_v + ((size_t)b * HW + pix0) * VD;
#pragma unroll
    for (int t = 0; t < 2; t++) {
#pragma unroll
        for (int h = 0; h < 2; h++) {
            *reinterpret_cast<float2*>(vb + (4 * gid + 2 * t) * VD + h * 8 + 2 * tg) =
                make_float2(d[t][h][0], d[t][h][1]);
            *reinterpret_cast<float2*>(vb + (4 * gid + 2 * t + 1) * VD + h * 8 + 2 * tg) =
                make_float2(d[t][h][2], d[t][h][3]);
        }
    }

    // ---- pooled sums over this warp's 32 pixels, per out column ----
    float s2[2][2];
#pragma unroll
    for (int h = 0; h < 2; h++) {
        s2[h][0] = d[0][h][0] + d[0][h][2] + d[1][h][0] + d[1][h][2];
        s2[h][1] = d[0][h][1] + d[0][h][3] + d[1][h][1] + d[1][h][3];
    }
#pragma unroll
    for (int off = 4; off < 32; off <<= 1) {
#pragma unroll
        for (int h = 0; h < 2; h++) {
            s2[h][0] += __shfl_xor_sync(0xffffffffu, s2[h][0], off);
            s2[h][1] += __shfl_xor_sync(0xffffffffu, s2[h][1], off);
        }
    }
    if (gid == 0) {
#pragma unroll
        for (int h = 0; h < 2; h++) {
            sred[warp][h * 8 + 2 * tg]     = s2[h][0];
            sred[warp][h * 8 + 2 * tg + 1] = s2[h][1];
        }
    }
    __syncthreads();
    if (tid < VD) {
        float t = 0.f;
#pragma unroll
        for (int w = 0; w < 8; w++) t += sred[w][tid];
        g_part[blockIdx.x * VD + tid] = t;
    }
}

// ======================================================================
// Pass 2 (fused tree + head + finisher): every block recomputes the tiny
// tree from g_part, runs the per-pixel head on its 512-pixel chunk; the
// last block (ticket) also reduces g_m2part -> mantissa. grid 256.
// ======================================================================
__global__ void __launch_bounds__(256) k_headtree(const float* __restrict__ root_b,
                                                  const float* __restrict__ level_w,
                                                  const float* __restrict__ level_b,
                                                  const float* __restrict__ m1_w,
                                                  const float* __restrict__ m1_b,
                                                  const float* __restrict__ m2_w,
                                                  const float* __restrict__ m2_b,
                                                  float* __restrict__ out) {
    const int b = blockIdx.x >> 3, chunk = blockIdx.x & 7;
    const int tid = threadIdx.x;

    // ---- tree phase (smem) ----
    __shared__ float A[NCLS][VD][VD], Cv[NCLS][VD], Mu[NCLS][VD];
    __shared__ float An[NCLS][VD][VD], Cn[NCLS][VD], Mun[NCLS][VD];
    __shared__ float norms[NCLS];
    __shared__ int selsh;

    {
        int o = tid >> 4, i = tid & 15;
        A[0][o][i] = (o == i) ? 1.f : 0.f;
    }
    if (tid < VD) {
        float s = 0.f;
        for (int ch = 0; ch < 16; ch++) s += g_part[(b * 16 + ch) * VD + tid];
        Mu[0][tid] = s * (1.0f / (float)HW) + root_b[tid];
        Cv[0][tid] = 0.f;
    }
    __syncthreads();

    for (int level = 1; level < NCLS; level++) {
        const int prevN = level, newN = level + 1;
        const int off = ((level - 1) * (level + 2)) >> 1;   // 0,2,5,9

        if (tid < prevN) {
            float s = 0.f;
            for (int k = 0; k < VD; k++) s += Mu[tid][k] * Mu[tid][k];
            norms[tid] = sqrtf(s);
        }
        __syncthreads();

        if (tid < newN * VD) {
            const int node = tid >> 4, o = tid & 15;
            int pl = node - 1; if (pl < 0) pl = 0;
            int pr = node;     if (pr > prevN - 1) pr = prevN - 1;
            const int ps = (pl == pr) ? pl : ((norms[pr] > norms[pl]) ? pr : pl);

            const float* W = level_w + (off + node) * (VD * VD) + o * VD;
            const float bb = level_b[(off + node) * VD + o];
            float cm = bb, mm = bb;
            float arow[VD];
#pragma unroll
            for (int i = 0; i < VD; i++) arow[i] = 0.f;
            for (int k = 0; k < VD; k++) {
                const float w = W[k];
                cm += w * Cv[ps][k];
                mm += w * Mu[ps][k];
#pragma unroll
                for (int i = 0; i < VD; i++) arow[i] += w * A[ps][k][i];
            }
            Cn[node][o] = cm;
            Mun[node][o] = mm;
#pragma unroll
            for (int i = 0; i < VD; i++) An[node][o][i] = arow[i];
        }
        __syncthreads();

        for (int idx = tid; idx < newN * VD * VD; idx += 256) {
            int node = idx >> 8, r = idx & 255;
            A[node][r >> 4][r & 15] = An[node][r >> 4][r & 15];
        }
        if (tid < newN * VD) {
            Cv[tid >> 4][tid & 15] = Cn[tid >> 4][tid & 15];
            Mu[tid >> 4][tid & 15] = Mun[tid >> 4][tid & 15];
        }
        __syncthreads();
    }

    if (tid < NCLS) {
        float s = 0.f;
        for (int k = 0; k < VD; k++) s += Mu[tid][k] * Mu[tid][k];
        norms[tid] = sqrtf(s);
        if (chunk == 0) out[b * NCLS + tid] = norms[tid];
    }
    __syncthreads();
    if (tid == 0) {
        int sel = 0; float best = norms[0];
        for (int n = 1; n < NCLS; n++) if (norms[n] > best) { best = norms[n]; sel = n; }
        selsh = sel;
        if (chunk == 0) out[B * NCLS + B + b] = (float)sel;
    }
    __syncthreads();
    const int sel = selsh;

    // ---- head setup: duplicated-pair weights in smem ----
    __shared__ ULL sAp[VD * VD];
    __shared__ ULL sdp[VD];
    __shared__ ULL sw1p[64 * VD];
    __shared__ ULL sb1p[64];
    __shared__ float sw2[64];
    __shared__ float sb2;

    {
        float a = A[sel][tid >> 4][tid & 15];
        sAp[tid] = pack2(a, a);
    }
    for (int i = tid; i < 64 * VD; i += 256) {
        float w = m1_w[i];
        sw1p[i] = pack2(w, w);
    }
    if (tid < 64) {
        float bb = m1_b[tid];
        sb1p[tid] = pack2(bb, bb);
        sw2[tid] = m2_w[tid];
    }
    if (tid < VD) {
        float s = Cv[sel][tid];
        for (int k = 0; k < VD; k++) s += A[sel][tid][k] * root_b[k];
        sdp[tid] = pack2(s, s);
    }
    if (tid == 0) sb2 = m2_b[0];
    __syncthreads();

    // ---- head phase: 2 pixels/thread, f32x2-packed ----
    const int pix0 = chunk * 512 + tid * 2;
    const float4* vp = reinterpret_cast<const float4*>(g_v + ((size_t)b * HW + pix0) * VD);

    float va0[VD], va1[VD];
#pragma unroll
    for (int q = 0; q < 4; q++) {
        float4 t0 = vp[q], t1 = vp[4 + q];
        va0[4*q+0] = t0.x; va0[4*q+1] = t0.y; va0[4*q+2] = t0.z; va0[4*q+3] = t0.w;
        va1[4*q+0] = t1.x; va1[4*q+1] = t1.y; va1[4*q+2] = t1.z; va1[4*q+3] = t1.w;
    }
    ULL v2[VD];
#pragma unroll
    for (int k = 0; k < VD; k++) v2[k] = pack2(va0[k], va1[k]);

    ULL f2[VD];
#pragma unroll
    for (int o = 0; o < VD; o++) {
        ULL t = sdp[o];
#pragma unroll
        for (int k = 0; k < VD; k++) t = ffma2(sAp[o * VD + k], v2[k], t);
        f2[o] = t;
    }

    float n20 = 0.f, n21 = 0.f;
#pragma unroll
    for (int o = 0; o < VD; o++) {
        float2 t = unpack2(f2[o]);
        n20 += t.x * t.x; n21 += t.y * t.y;
    }
    const ULL inv2 = pack2(1.0f / (sqrtf(n20) + 1e-8f),
                           1.0f / (sqrtf(n21) + 1e-8f));

    float m2a0 = 0.f, m2a1 = 0.f;
#pragma unroll 8
    for (int j = 0; j < 64; j++) {
        ULL t2 = pack2(0.f, 0.f);
#pragma unroll
        for (int o = 0; o < VD; o++) t2 = ffma2(sw1p[j * VD + o], f2[o], t2);
        t2 = ffma2(t2, inv2, sb1p[j]);
        float2 t = unpack2(t2);
        m2a0 += sw2[j] * fmaxf(t.x, 0.f);
        m2a1 += sw2[j] * fmaxf(t.y, 0.f);
    }
    float ssum = (m2a0 + m2a1) + 2.0f * sb2;

    __shared__ float red[8];
    __shared__ int is_last;
    const int lane = tid & 31, wid = tid >> 5;
#pragma unroll
    for (int off = 16; off; off >>= 1) ssum += __shfl_xor_sync(0xffffffffu, ssum, off);
    if (lane == 0) red[wid] = ssum;
    __syncthreads();
    if (tid == 0) {
        float t = 0.f;
#pragma unroll
        for (int w = 0; w < 8; w++) t += red[w];
        g_m2part[blockIdx.x] = t;
        __threadfence();
        int tk = atomicAdd(&g_ticket, 1);
        is_last = (tk == 255);
    }
    __syncthreads();

    // ---- finisher: last block computes mantissa for all batches ----
    if (is_last) {
        __threadfence();
        if (tid < B) {
            float s = 0.f;
#pragma unroll
            for (int c = 0; c < 8; c++) s += g_m2part[tid * 8 + c];
            const float x = s * (1.0f / (float)HW);
            out[B * NCLS + tid] = 0.75f / (1.0f + expf(-x)) + 0.75f;
        }
        if (tid == 0) g_ticket = 0;   // replay-safe reset
    }
}

// ======================================================================
extern "C" void kernel_launch(void* const* d_in, const int* in_sizes, int n_in,
                              void* d_out, int out_size) {
    const float* features = (const float*)d_in[0];
    const float* root_w   = (const float*)d_in[1];
    const float* root_b   = (const float*)d_in[2];
    const float* level_w  = (const float*)d_in[3];
    const float* level_b  = (const float*)d_in[4];
    const float* m1_w     = (const float*)d_in[5];
    const float* m1_b     = (const float*)d_in[6];
    const float* m2_w     = (const float*)d_in[7];
    const float* m2_b     = (const float*)d_in[8];
    float* out = (float*)d_out;

    k_root<<<B * 16, 256>>>(features, root_w);
    k_headtree<<<B * 8, 256>>>(root_b, level_w, level_b, m1_w, m1_b, m2_w, m2_b, out);
}